// round 5
// baseline (speedup 1.0000x reference)
#include <cuda_runtime.h>
#include <cuda_fp16.h>
#include <math.h>

// Problem constants
#define NEXP 64
#define TOPK 4
#define HDIM 2048
#define IDIM 1536
#define GSZ  128
#define NTOK 1024
#define CAP  128
#define A_TOT (NTOK*TOPK)        // 4096 assignments
#define NCHUNK (A_TOT/256)       // 16
#define HW   (HDIM/8)            // 256 packed words per gate/up row
#define IW   (IDIM/8)            // 192 packed words per down row
#define NGH  (HDIM/GSZ)          // 16
#define NGI  (IDIM/GSZ)          // 12

// Scratch (static device globals; no runtime allocation)
__device__ int    g_topk_idx[A_TOT];
__device__ float  g_topk_w[A_TOT];
__device__ int    g_pos[A_TOT];
__device__ int    g_rowlist[NEXP*CAP];
__device__ int    g_count[NEXP];
__device__ int    g_chunkhist[NCHUNK][NEXP];
__device__ __half g_xh[(size_t)NTOK*HDIM];          // x in fp16
__device__ __half g_hbh[(size_t)NEXP*CAP*IDIM];     // routed h (fp16)
__device__ __half g_hshh[(size_t)NTOK*IDIM];        // shared h (fp16)
__device__ float  g_yrout[(size_t)NEXP*CAP*HDIM];   // routed down output

// ---------------------------------------------------------------------------
// helpers
// ---------------------------------------------------------------------------
__device__ __forceinline__ unsigned sptr(const void* p) {
    return (unsigned)__cvta_generic_to_shared(p);
}

__device__ __forceinline__ void ldsm4(unsigned a, unsigned& r0, unsigned& r1,
                                      unsigned& r2, unsigned& r3) {
    asm volatile("ldmatrix.sync.aligned.m8n8.x4.shared.b16 {%0,%1,%2,%3}, [%4];"
                 : "=r"(r0), "=r"(r1), "=r"(r2), "=r"(r3) : "r"(a));
}

__device__ __forceinline__ void mma16816(float* c, const unsigned* a,
                                         unsigned b0, unsigned b1) {
    asm volatile("mma.sync.aligned.m16n8k16.row.col.f32.f16.f16.f32 "
                 "{%0,%1,%2,%3},{%4,%5,%6,%7},{%8,%9},{%0,%1,%2,%3};"
                 : "+f"(c[0]), "+f"(c[1]), "+f"(c[2]), "+f"(c[3])
                 : "r"(a[0]), "r"(a[1]), "r"(a[2]), "r"(a[3]), "r"(b0), "r"(b1));
}

// FP4 e2m1 nibble b -> fp16 bits ((b&7)<<9 | (b&8)<<12); value = fp16 * 2^14.
// Scale pre-multiplied by 2^14. Produces 4 half2 (k-pairs 01,23,45,67).
__device__ __forceinline__ void dq8(unsigned w, __half2 s, unsigned* o) {
    unsigned lo = w & 0x0F0F0F0Fu;
    unsigned hi = (w >> 4) & 0x0F0F0F0Fu;
    unsigned fl = ((lo << 1) & 0x0E0E0E0Eu) | ((lo << 4) & 0x80808080u);
    unsigned fh = ((hi << 1) & 0x0E0E0E0Eu) | ((hi << 4) & 0x80808080u);
    unsigned m0 = __byte_perm(fl, fh, 0x5140);
    unsigned m1 = __byte_perm(fl, fh, 0x7362);
    unsigned t0 = __byte_perm(m0, 0, 0x1404);
    unsigned t1 = __byte_perm(m0, 0, 0x3424);
    unsigned t2 = __byte_perm(m1, 0, 0x1404);
    unsigned t3 = __byte_perm(m1, 0, 0x3424);
    __half2 h0 = __hmul2(*reinterpret_cast<__half2*>(&t0), s);
    __half2 h1 = __hmul2(*reinterpret_cast<__half2*>(&t1), s);
    __half2 h2 = __hmul2(*reinterpret_cast<__half2*>(&t2), s);
    __half2 h3 = __hmul2(*reinterpret_cast<__half2*>(&t3), s);
    o[0] = *reinterpret_cast<unsigned*>(&h0);
    o[1] = *reinterpret_cast<unsigned*>(&h1);
    o[2] = *reinterpret_cast<unsigned*>(&h2);
    o[3] = *reinterpret_cast<unsigned*>(&h3);
}

__device__ __forceinline__ float silu_f(float v) {
    return v / (1.f + expf(-v));
}

// ---------------------------------------------------------------------------
__global__ __launch_bounds__(256) void xcvt_kernel(const float* __restrict__ x)
{
    size_t i = ((size_t)blockIdx.x * 256 + threadIdx.x) * 4;
    float4 v = *(const float4*)(x + i);
    *(__half2*)&g_xh[i]     = __floats2half2_rn(v.x, v.y);
    *(__half2*)&g_xh[i + 2] = __floats2half2_rn(v.z, v.w);
}

// ---------------------------------------------------------------------------
// Router (fp32 exact top-k)
// ---------------------------------------------------------------------------
__global__ __launch_bounds__(256) void router_kernel(const float* __restrict__ x,
                                                     const float* __restrict__ gate_w)
{
    __shared__ float sx[16][33];
    __shared__ float sw[64][33];
    __shared__ float slog[16][65];
    int t0  = blockIdx.x * 16;
    int tid = threadIdx.x;
    int e   = tid & 63;
    int tg  = tid >> 6;
    float acc[4] = {0.f, 0.f, 0.f, 0.f};

    for (int hc = 0; hc < HDIM; hc += 32) {
        __syncthreads();
#pragma unroll
        for (int k = 0; k < 8; k++) {
            int idx = tid + k * 256;
            sw[idx >> 5][idx & 31] = gate_w[(idx >> 5) * HDIM + hc + (idx & 31)];
        }
#pragma unroll
        for (int k = 0; k < 2; k++) {
            int idx = tid + k * 256;
            sx[idx >> 5][idx & 31] = x[(size_t)(t0 + (idx >> 5)) * HDIM + hc + (idx & 31)];
        }
        __syncthreads();
#pragma unroll 8
        for (int kk = 0; kk < 32; kk++) {
            float wv = sw[e][kk];
#pragma unroll
            for (int j = 0; j < 4; j++) acc[j] += sx[tg * 4 + j][kk] * wv;
        }
    }
#pragma unroll
    for (int j = 0; j < 4; j++) slog[tg * 4 + j][e] = acc[j];
    __syncthreads();

    if (tid < 16) {
        int tt = tid;
        unsigned long long used = 0ull;
        int idxk[TOPK]; float valk[TOPK];
#pragma unroll
        for (int k = 0; k < TOPK; k++) {
            float bv = -1e30f; int bi = 0;
            for (int ee = 0; ee < NEXP; ee++) {
                float v = slog[tt][ee];
                if (((used >> ee) & 1ull) == 0 && v > bv) { bv = v; bi = ee; }
            }
            used |= (1ull << bi);
            idxk[k] = bi; valk[k] = bv;
        }
        float s = 0.f, w[TOPK];
#pragma unroll
        for (int k = 0; k < TOPK; k++) { w[k] = expf(valk[k] - valk[0]); s += w[k]; }
#pragma unroll
        for (int k = 0; k < TOPK; k++) {
            g_topk_idx[(t0 + tt) * TOPK + k] = idxk[k];
            g_topk_w[(t0 + tt) * TOPK + k]  = w[k] / s;
        }
    }
}

__global__ void zero_counts_kernel()
{
    if (threadIdx.x < NEXP) g_count[threadIdx.x] = 0;
}

// ---------------------------------------------------------------------------
// Dispatch stage 1: per-chunk expert histograms (+ global counts).
// ---------------------------------------------------------------------------
__global__ __launch_bounds__(256) void hist_kernel()
{
    __shared__ int cnt[NEXP];
    int tid = threadIdx.x;
    if (tid < NEXP) cnt[tid] = 0;
    __syncthreads();
    int e = g_topk_idx[blockIdx.x * 256 + tid];
    atomicAdd(&cnt[e], 1);
    __syncthreads();
    if (tid < NEXP) {
        g_chunkhist[blockIdx.x][tid] = cnt[tid];
        atomicAdd(&g_count[tid], cnt[tid]);
    }
}

// ---------------------------------------------------------------------------
// Dispatch stage 2: pos[a] = (#same-expert in earlier chunks) + within-chunk
// prefix count. Matches stable argsort semantics exactly.
// ---------------------------------------------------------------------------
__global__ __launch_bounds__(256) void dispatch_kernel()
{
    __shared__ unsigned char ef[256];
    int tid = threadIdx.x;
    int a = blockIdx.x * 256 + tid;
    int e = g_topk_idx[a];
    ef[tid] = (unsigned char)e;
    __syncthreads();

    int base = 0;
    for (int c = 0; c < (int)blockIdx.x; c++) base += g_chunkhist[c][e];
    int local = 0;
    for (int j = 0; j < tid; j++) local += (ef[j] == (unsigned char)e) ? 1 : 0;
    int p = base + local;
    g_pos[a] = p;
    if (p < CAP) g_rowlist[e * CAP + p] = a;
}

// ---------------------------------------------------------------------------
// GEMM1 (tensor cores): h = silu(x Wg^T) * (x Wu^T). Tile 128(M) x 64(N),
// K-chunk 64. 8 warps in 4(M) x 2(N) grid; each warp owns 32x32.
// ROUTED: one pass covers up to CAP=128 rows -> each weight dequanted once.
// ---------------------------------------------------------------------------
template<bool ROUTED>
__global__ __launch_bounds__(256) void gemm1_mma(
    const int* __restrict__ gpk, const int* __restrict__ upk,
    const float* __restrict__ gsc, const float* __restrict__ usc)
{
    __shared__ __half sX [128][72];
    __shared__ __half sWg[64][72];
    __shared__ __half sWu[64][72];
    __shared__ int srows[128];

    int tid = threadIdx.x;
    int ic0 = blockIdx.y * 64;
    int e   = blockIdx.x;

    int n; const int *gp, *up; const float *gs, *us;
    if (ROUTED) {
        n  = min(g_count[e], CAP);
        if (n == 0) return;
        gp = gpk + (size_t)e * IDIM * HW;
        up = upk + (size_t)e * IDIM * HW;
        gs = gsc + (size_t)e * NGH * IDIM;
        us = usc + (size_t)e * NGH * IDIM;
    } else { n = 128; gp = gpk; up = upk; gs = gsc; us = usc; }

    __half* hout = ROUTED ? g_hbh : g_hshh;
    int rbase    = ROUTED ? e * CAP : e * 128;

    if (ROUTED) {
        if (tid < 128)
            srows[tid] = (tid < n) ? (g_rowlist[e * CAP + tid] >> 2) : 0;
        __syncthreads();
    }

    int w = tid >> 5, l = tid & 31;
    int mb = (w & 3) * 32, nb = (w >> 2) * 32;
    // X loader mapping: 128 rows x 64 cols, 32 halves (4 x uint4) per thread
    int xrow = tid >> 1, xhalf = tid & 1;
    // weight loader mapping: 64 N-rows x 64 K, 2 words x2 matrices per thread
    int wrow = tid >> 2, wseg = tid & 3;
    int i_w  = ic0 + wrow;

    int tok;
    if (ROUTED) tok = srows[min(xrow, n - 1)];
    else        tok = e * 128 + xrow;

    float accg[2][4][4], accu[2][4][4];
#pragma unroll
    for (int i = 0; i < 2; i++)
#pragma unroll
        for (int j = 0; j < 4; j++)
#pragma unroll
            for (int q = 0; q < 4; q++) { accg[i][j][q] = 0.f; accu[i][j][q] = 0.f; }

    uint4 xa[4]; int2 gw, uw; float sgf, suf;
    auto LOAD = [&](int kc) {
        const uint4* xp = (const uint4*)(g_xh + (size_t)tok * HDIM + kc + xhalf * 32);
#pragma unroll
        for (int j = 0; j < 4; j++) xa[j] = xp[j];
        gw = ((const int2*)(gp + (size_t)i_w * HW + (kc >> 3)))[wseg];
        uw = ((const int2*)(up + (size_t)i_w * HW + (kc >> 3)))[wseg];
        int grp = kc >> 7;
        sgf = gs[grp * IDIM + i_w];
        suf = us[grp * IDIM + i_w];
    };
    auto STORE = [&]() {
#pragma unroll
        for (int j = 0; j < 4; j++)
            *(uint4*)&sX[xrow][xhalf * 32 + j * 8] = xa[j];
        __half2 s2g = __float2half2_rn(sgf * 16384.f);
        __half2 s2u = __float2half2_rn(suf * 16384.f);
        unsigned o[4];
        dq8((unsigned)gw.x, s2g, o);
        *(uint2*)&sWg[wrow][wseg * 16]      = make_uint2(o[0], o[1]);
        *(uint2*)&sWg[wrow][wseg * 16 + 4]  = make_uint2(o[2], o[3]);
        dq8((unsigned)gw.y, s2g, o);
        *(uint2*)&sWg[wrow][wseg * 16 + 8]  = make_uint2(o[0], o[1]);
        *(uint2*)&sWg[wrow][wseg * 16 + 12] = make_uint2(o[2], o[3]);
        dq8((unsigned)uw.x, s2u, o);
        *(uint2*)&sWu[wrow][wseg * 16]      = make_uint2(o[0], o[1]);
        *(uint2*)&sWu[wrow][wseg * 16 + 4]  = make_uint2(o[2], o[3]);
        dq8((unsigned)uw.y, s2u, o);
        *(uint2*)&sWu[wrow][wseg * 16 + 8]  = make_uint2(o[0], o[1]);
        *(uint2*)&sWu[wrow][wseg * 16 + 12] = make_uint2(o[2], o[3]);
    };

    LOAD(0);
    for (int c = 0; c < HDIM / 64; c++) {
        __syncthreads();
        STORE();
        __syncthreads();
        if (c + 1 < HDIM / 64) LOAD((c + 1) * 64);
#pragma unroll
        for (int ks = 0; ks < 4; ks++) {
            int k0 = ks * 16;
            unsigned a0[4], a1[4], bg0[4], bg1[4], bu0[4], bu1[4];
            ldsm4(sptr(&sX[mb      + (l & 7) + ((l >> 3) & 1) * 8][k0 + (l >> 4) * 8]),
                  a0[0], a0[1], a0[2], a0[3]);
            ldsm4(sptr(&sX[mb + 16 + (l & 7) + ((l >> 3) & 1) * 8][k0 + (l >> 4) * 8]),
                  a1[0], a1[1], a1[2], a1[3]);
            ldsm4(sptr(&sWg[nb      + ((l >> 4) << 3) + (l & 7)][k0 + ((l >> 3) & 1) * 8]),
                  bg0[0], bg0[1], bg0[2], bg0[3]);
            ldsm4(sptr(&sWg[nb + 16 + ((l >> 4) << 3) + (l & 7)][k0 + ((l >> 3) & 1) * 8]),
                  bg1[0], bg1[1], bg1[2], bg1[3]);
            ldsm4(sptr(&sWu[nb      + ((l >> 4) << 3) + (l & 7)][k0 + ((l >> 3) & 1) * 8]),
                  bu0[0], bu0[1], bu0[2], bu0[3]);
            ldsm4(sptr(&sWu[nb + 16 + ((l >> 4) << 3) + (l & 7)][k0 + ((l >> 3) & 1) * 8]),
                  bu1[0], bu1[1], bu1[2], bu1[3]);
            mma16816(accg[0][0], a0, bg0[0], bg0[1]);
            mma16816(accg[0][1], a0, bg0[2], bg0[3]);
            mma16816(accg[0][2], a0, bg1[0], bg1[1]);
            mma16816(accg[0][3], a0, bg1[2], bg1[3]);
            mma16816(accg[1][0], a1, bg0[0], bg0[1]);
            mma16816(accg[1][1], a1, bg0[2], bg0[3]);
            mma16816(accg[1][2], a1, bg1[0], bg1[1]);
            mma16816(accg[1][3], a1, bg1[2], bg1[3]);
            mma16816(accu[0][0], a0, bu0[0], bu0[1]);
            mma16816(accu[0][1], a0, bu0[2], bu0[3]);
            mma16816(accu[0][2], a0, bu1[0], bu1[1]);
            mma16816(accu[0][3], a0, bu1[2], bu1[3]);
            mma16816(accu[1][0], a1, bu0[0], bu0[1]);
            mma16816(accu[1][1], a1, bu0[2], bu0[3]);
            mma16816(accu[1][2], a1, bu1[0], bu1[1]);
            mma16816(accu[1][3], a1, bu1[2], bu1[3]);
        }
    }

    // epilogue: silu(g)*u -> fp16
    int qm = l >> 2, qn = (l & 3) * 2;
#pragma unroll
    for (int mi = 0; mi < 2; mi++)
#pragma unroll
        for (int nf = 0; nf < 4; nf++) {
            int lr   = mb + mi * 16 + qm;
            int icol = ic0 + nb + nf * 8 + qn;
            float* g4 = accg[mi][nf]; float* u4 = accu[mi][nf];
            if (!ROUTED || lr < n) {
                float h0 = silu_f(g4[0]) * u4[0];
                float h1 = silu_f(g4[1]) * u4[1];
                *(__half2*)&hout[(size_t)(rbase + lr) * IDIM + icol] =
                    __floats2half2_rn(h0, h1);
            }
            if (!ROUTED || lr + 8 < n) {
                float h2 = silu_f(g4[2]) * u4[2];
                float h3 = silu_f(g4[3]) * u4[3];
                *(__half2*)&hout[(size_t)(rbase + lr + 8) * IDIM + icol] =
                    __floats2half2_rn(h2, h3);
            }
        }
}

// ---------------------------------------------------------------------------
// GEMM2 (tensor cores): y = h @ Wd^T. Tile 128(M) x 64(N), K-chunk 64.
// ---------------------------------------------------------------------------
template<bool ROUTED>
__global__ __launch_bounds__(256) void gemm2_mma(
    const int* __restrict__ dpk, const float* __restrict__ dsc,
    float* __restrict__ y)
{
    __shared__ __half sH[128][72];
    __shared__ __half sW[64][72];

    int tid = threadIdx.x;
    int oc0 = blockIdx.y * 64;
    int e   = blockIdx.x;

    int n; const int* dp; const float* ds;
    if (ROUTED) {
        n  = min(g_count[e], CAP);
        if (n == 0) return;
        dp = dpk + (size_t)e * HDIM * IW;
        ds = dsc + (size_t)e * NGI * HDIM;
    } else { n = 128; dp = dpk; ds = dsc; }

    const __half* hin = ROUTED ? g_hbh : g_hshh;
    float* yout       = ROUTED ? g_yrout : y;
    int rbase         = ROUTED ? e * CAP : e * 128;

    int w = tid >> 5, l = tid & 31;
    int mb = (w & 3) * 32, nb = (w >> 2) * 32;
    int xrow = tid >> 1, xhalf = tid & 1;
    int wrow = tid >> 2, wseg = tid & 3;
    int o_w  = oc0 + wrow;

    int hr = rbase + (ROUTED ? min(xrow, n - 1) : xrow);

    float acc[2][4][4];
#pragma unroll
    for (int i = 0; i < 2; i++)
#pragma unroll
        for (int j = 0; j < 4; j++)
#pragma unroll
            for (int q = 0; q < 4; q++) acc[i][j][q] = 0.f;

    uint4 ha[4]; int2 dw; float sdf;
    auto LOAD = [&](int kc) {
        const uint4* hp = (const uint4*)(hin + (size_t)hr * IDIM + kc + xhalf * 32);
#pragma unroll
        for (int j = 0; j < 4; j++) ha[j] = hp[j];
        dw = ((const int2*)(dp + (size_t)o_w * IW + (kc >> 3)))[wseg];
        sdf = ds[(kc >> 7) * HDIM + o_w];
    };
    auto STORE = [&]() {
#pragma unroll
        for (int j = 0; j < 4; j++)
            *(uint4*)&sH[xrow][xhalf * 32 + j * 8] = ha[j];
        __half2 s2 = __float2half2_rn(sdf * 16384.f);
        unsigned o[4];
        dq8((unsigned)dw.x, s2, o);
        *(uint2*)&sW[wrow][wseg * 16]      = make_uint2(o[0], o[1]);
        *(uint2*)&sW[wrow][wseg * 16 + 4]  = make_uint2(o[2], o[3]);
        dq8((unsigned)dw.y, s2, o);
        *(uint2*)&sW[wrow][wseg * 16 + 8]  = make_uint2(o[0], o[1]);
        *(uint2*)&sW[wrow][wseg * 16 + 12] = make_uint2(o[2], o[3]);
    };

    LOAD(0);
    for (int c = 0; c < IDIM / 64; c++) {
        __syncthreads();
        STORE();
        __syncthreads();
        if (c + 1 < IDIM / 64) LOAD((c + 1) * 64);
#pragma unroll
        for (int ks = 0; ks < 4; ks++) {
            int k0 = ks * 16;
            unsigned a0[4], a1[4], b0[4], b1[4];
            ldsm4(sptr(&sH[mb      + (l & 7) + ((l >> 3) & 1) * 8][k0 + (l >> 4) * 8]),
                  a0[0], a0[1], a0[2], a0[3]);
            ldsm4(sptr(&sH[mb + 16 + (l & 7) + ((l >> 3) & 1) * 8][k0 + (l >> 4) * 8]),
                  a1[0], a1[1], a1[2], a1[3]);
            ldsm4(sptr(&sW[nb      + ((l >> 4) << 3) + (l & 7)][k0 + ((l >> 3) & 1) * 8]),
                  b0[0], b0[1], b0[2], b0[3]);
            ldsm4(sptr(&sW[nb + 16 + ((l >> 4) << 3) + (l & 7)][k0 + ((l >> 3) & 1) * 8]),
                  b1[0], b1[1], b1[2], b1[3]);
            mma16816(acc[0][0], a0, b0[0], b0[1]);
            mma16816(acc[0][1], a0, b0[2], b0[3]);
            mma16816(acc[0][2], a0, b1[0], b1[1]);
            mma16816(acc[0][3], a0, b1[2], b1[3]);
            mma16816(acc[1][0], a1, b0[0], b0[1]);
            mma16816(acc[1][1], a1, b0[2], b0[3]);
            mma16816(acc[1][2], a1, b1[0], b1[1]);
            mma16816(acc[1][3], a1, b1[2], b1[3]);
        }
    }

    int qm = l >> 2, qn = (l & 3) * 2;
#pragma unroll
    for (int mi = 0; mi < 2; mi++)
#pragma unroll
        for (int nf = 0; nf < 4; nf++) {
            int lr   = mb + mi * 16 + qm;
            int ocol = oc0 + nb + nf * 8 + qn;
            float* c4 = acc[mi][nf];
            if (!ROUTED || lr < n)
                *(float2*)&yout[(size_t)(rbase + lr) * HDIM + ocol] =
                    make_float2(c4[0], c4[1]);
            if (!ROUTED || lr + 8 < n)
                *(float2*)&yout[(size_t)(rbase + lr + 8) * HDIM + ocol] =
                    make_float2(c4[2], c4[3]);
        }
}

// ---------------------------------------------------------------------------
// Combine: y[t] += sum_k tw[t,k] * yrout[slot(t,k)]
// ---------------------------------------------------------------------------
__global__ __launch_bounds__(256) void combine_kernel(float* __restrict__ y)
{
    int t = blockIdx.x;
    __shared__ int   slot4[TOPK];
    __shared__ float w4[TOPK];
    int tid = threadIdx.x;
    if (tid < TOPK) {
        int a = t * TOPK + tid;
        int e = g_topk_idx[a];
        int p = g_pos[a];
        slot4[tid] = (p < CAP) ? (e * CAP + p) : -1;
        w4[tid]    = g_topk_w[a];
    }
    __syncthreads();
    for (int hh = tid; hh < HDIM; hh += 256) {
        float acc = y[(size_t)t * HDIM + hh];
#pragma unroll
        for (int k = 0; k < TOPK; k++) {
            int s = slot4[k];
            if (s >= 0) acc += w4[k] * g_yrout[(size_t)s * HDIM + hh];
        }
        y[(size_t)t * HDIM + hh] = acc;
    }
}

// ---------------------------------------------------------------------------
extern "C" void kernel_launch(void* const* d_in, const int* in_sizes, int n_in,
                              void* d_out, int out_size)
{
    const float* x              = (const float*)d_in[0];
    const float* gate_w         = (const float*)d_in[1];
    const float* gate_scales    = (const float*)d_in[2];
    const float* up_scales      = (const float*)d_in[3];
    const float* down_scales    = (const float*)d_in[4];
    const float* sh_gate_scales = (const float*)d_in[5];
    const float* sh_up_scales   = (const float*)d_in[6];
    const float* sh_down_scales = (const float*)d_in[7];
    const int*   gate_packed    = (const int*)d_in[8];
    const int*   up_packed      = (const int*)d_in[9];
    const int*   down_packed    = (const int*)d_in[10];
    const int*   sh_gate_packed = (const int*)d_in[11];
    const int*   sh_up_packed   = (const int*)d_in[12];
    const int*   sh_down_packed = (const int*)d_in[13];
    float* y = (float*)d_out;

    xcvt_kernel<<<NTOK * HDIM / 1024, 256>>>(x);
    router_kernel<<<NTOK / 16, 256>>>(x, gate_w);
    zero_counts_kernel<<<1, 64>>>();
    hist_kernel<<<NCHUNK, 256>>>();
    dispatch_kernel<<<NCHUNK, 256>>>();

    // Shared expert
    gemm1_mma<false><<<dim3(NTOK / 128, IDIM / 64), 256>>>(
        sh_gate_packed, sh_up_packed, sh_gate_scales, sh_up_scales);
    gemm2_mma<false><<<dim3(NTOK / 128, HDIM / 64), 256>>>(
        sh_down_packed, sh_down_scales, y);

    // Routed experts (single pass per expert: M tile = CAP)
    gemm1_mma<true><<<dim3(NEXP, IDIM / 64), 256>>>(
        gate_packed, up_packed, gate_scales, up_scales);
    gemm2_mma<true><<<dim3(NEXP, HDIM / 64), 256>>>(
        down_packed, down_scales, y);

    combine_kernel<<<NTOK, 256>>>(y);
}